// round 14
// baseline (speedup 1.0000x reference)
#include <cuda_runtime.h>
#include <cuda_bf16.h>
#include <cstdint>

// Problem constants (fixed by the reference)
#define N_TOK 16384      // B*S = 8*2048
#define D_DIM 4096
#define D_VEC 1024       // D/4 float4 per row
#define N_EXP 8
#define CAP   2048       // capacity = B*S/E
#define MARGIN_TH 1e-4f  // inline fp64 re-rank threshold (noise ~1e-6)
#define CHUNK 32         // tokens per CTA
#define NCHUNK (N_TOK / CHUNK)   // 512

// Scratch (no device allocs allowed) ---------------------------------------
// Decoupled-lookback tile state. AGG and PREFIX live in separate arrays so a
// PREFIX publish never clobbers an AGG value another CTA is reading.
__device__ unsigned long long g_agg_lo[NCHUNK], g_agg_hi[NCHUNK];
__device__ unsigned long long g_pre_lo[NCHUNK], g_pre_hi[NCHUNK];
__device__ int g_flag[NCHUNK];   // 0=invalid 1=AGG 2=PREFIX (volatile access)
__device__ int g_cnt[N_EXP];     // per-expert totals (written by last chunk)

// ---------------------------------------------------------------------------
// Pass 0: reset lookback flags (graph replay safe)
// ---------------------------------------------------------------------------
__global__ void reset_kernel() {
    if (threadIdx.x < NCHUNK) g_flag[threadIdx.x] = 0;
}

// ---------------------------------------------------------------------------
// Fused kernel: per 32-token chunk (in token order):
//   1) route: 8 warps x 4 tokens, scalar fp32 (R12's 90.5us structure)
//   2) inline fp64 re-rank of marginal tokens (rare, ~0.8% of CTAs)
//   3) decoupled-lookback stable prefix -> global positions + capacity drop
//   4) copy kept rows x->out immediately (overlaps other CTAs' route FFMA)
// ---------------------------------------------------------------------------
__global__ void __launch_bounds__(256, 3) moe_fused_kernel(
    const float4* __restrict__ x,   // [N_TOK][1024]
    const float4* __restrict__ W,   // [8][1024]
    const float*  __restrict__ b,   // [8]
    float4* __restrict__ out)       // [N_TOK][1024]
{
    __shared__ int    sroute[CHUNK];
    __shared__ float  smarg[CHUNK];
    __shared__ int    sdst[CHUNK];
    __shared__ double sred[8][N_EXP];

    const int bid  = blockIdx.x;
    const int tid  = threadIdx.x;
    const int warp = tid >> 5;
    const int lane = tid & 31;
    const int tbase = bid * CHUNK + warp * 4;   // warp's first token

    // ---- phase 1: route (4 tokens/warp, W L1-resident) ----
    {
        const float4* x0 = x + (size_t)tbase * D_VEC;
        float acc[4][N_EXP];
#pragma unroll
        for (int t = 0; t < 4; t++)
#pragma unroll
            for (int e = 0; e < N_EXP; e++) acc[t][e] = 0.f;

        for (int i = 0; i < 32; i++) {
            const int idx = i * 32 + lane;
            float4 xv0 = __ldg(x0 + idx);
            float4 xv1 = __ldg(x0 + D_VEC + idx);
            float4 xv2 = __ldg(x0 + 2 * D_VEC + idx);
            float4 xv3 = __ldg(x0 + 3 * D_VEC + idx);
#pragma unroll
            for (int e = 0; e < N_EXP; e++) {
                float4 wv = __ldg(W + e * D_VEC + idx);
                acc[0][e] += xv0.x * wv.x + xv0.y * wv.y + xv0.z * wv.z + xv0.w * wv.w;
                acc[1][e] += xv1.x * wv.x + xv1.y * wv.y + xv1.z * wv.z + xv1.w * wv.w;
                acc[2][e] += xv2.x * wv.x + xv2.y * wv.y + xv2.z * wv.z + xv2.w * wv.w;
                acc[3][e] += xv3.x * wv.x + xv3.y * wv.y + xv3.z * wv.z + xv3.w * wv.w;
            }
        }
#pragma unroll
        for (int t = 0; t < 4; t++)
#pragma unroll
            for (int e = 0; e < N_EXP; e++) {
                float v = acc[t][e];
#pragma unroll
                for (int off = 16; off > 0; off >>= 1)
                    v += __shfl_xor_sync(0xFFFFFFFFu, v, off);
                acc[t][e] = v;
            }
        if (lane == 0) {
#pragma unroll
            for (int t = 0; t < 4; t++) {
                float best = -1e30f, second = -1e30f; int bi = 0;
#pragma unroll
                for (int e = 0; e < N_EXP; e++) {
                    float l = acc[t][e] + b[e];
                    if (l > best) { second = best; best = l; bi = e; }
                    else if (l > second) { second = l; }
                }
                sroute[warp * 4 + t] = bi;
                smarg [warp * 4 + t] = best - second;
            }
        }
    }
    __syncthreads();

    // ---- phase 2: inline fp64 re-rank of marginal tokens (rare) ----
    for (int k = 0; k < CHUNK; k++) {
        if (smarg[k] >= MARGIN_TH) continue;            // uniform across block
        const int tok = bid * CHUNK + k;
        const float* xr = (const float*)x + (size_t)tok * D_DIM;
        const float* Wf = (const float*)W;

        double p[N_EXP];
#pragma unroll
        for (int e = 0; e < N_EXP; e++) p[e] = 0.0;
        for (int d = tid; d < D_DIM; d += 256) {
            const double xv = (double)__ldg(xr + d);
#pragma unroll
            for (int e = 0; e < N_EXP; e++)
                p[e] += xv * (double)__ldg(Wf + e * D_DIM + d);
        }
#pragma unroll
        for (int e = 0; e < N_EXP; e++) {
            double v = p[e];
#pragma unroll
            for (int off = 16; off > 0; off >>= 1)
                v += __shfl_xor_sync(0xFFFFFFFFu, v, off);
            if (lane == 0) sred[warp][e] = v;
        }
        __syncthreads();
        if (tid == 0) {
            double best = -1e300; int bi = 0;
#pragma unroll
            for (int e = 0; e < N_EXP; e++) {
                double s = (double)b[e];
#pragma unroll
                for (int wi = 0; wi < 8; wi++) s += sred[wi][e];
                if (s > best) { best = s; bi = e; }     // strict > : first-max
            }
            sroute[k] = bi;
        }
        __syncthreads();
    }

    // ---- phase 3: decoupled-lookback stable prefix (warp 0) ----
    if (warp == 0) {
        const int r = sroute[lane];
        // rank among same-expert tokens earlier in this chunk (stable)
        const unsigned mmask = __match_any_sync(0xFFFFFFFFu, r);
        const int rank = __popc(mmask & ((1u << lane) - 1));

        // local per-expert counts packed as 2 x (4 x u16)
        unsigned long long loc_lo = 0, loc_hi = 0;
#pragma unroll
        for (int e = 0; e < 4; e++) {
            unsigned long long c = __popc(__ballot_sync(0xFFFFFFFFu, r == e));
            loc_lo |= c << (e * 16);
        }
#pragma unroll
        for (int e = 4; e < 8; e++) {
            unsigned long long c = __popc(__ballot_sync(0xFFFFFFFFu, r == e));
            loc_hi |= c << ((e - 4) * 16);
        }

        unsigned long long excl_lo = 0, excl_hi = 0;
        if (bid == 0) {
            if (lane == 0) {
                g_pre_lo[0] = loc_lo; g_pre_hi[0] = loc_hi;
                __threadfence();
                ((volatile int*)g_flag)[0] = 2;
            }
        } else {
            if (lane == 0) {
                g_agg_lo[bid] = loc_lo; g_agg_hi[bid] = loc_hi;
                __threadfence();
                ((volatile int*)g_flag)[bid] = 1;
            }
            // warp-parallel lookback over predecessor windows of 32
            int win = 0; bool done = false;
            while (!done) {
                const int look = bid - 1 - (win * 32 + lane);
                int f;
                do {
                    f = (look >= 0) ? ((volatile int*)g_flag)[look] : 2;
                } while (__ballot_sync(0xFFFFFFFFu, f >= 1) != 0xFFFFFFFFu);
                __threadfence();
                unsigned long long vlo = 0, vhi = 0;
                if (look >= 0) {
                    if (f == 2) {
                        vlo = ((volatile unsigned long long*)g_pre_lo)[look];
                        vhi = ((volatile unsigned long long*)g_pre_hi)[look];
                    } else {
                        vlo = ((volatile unsigned long long*)g_agg_lo)[look];
                        vhi = ((volatile unsigned long long*)g_agg_hi)[look];
                    }
                }
                const unsigned pmask = __ballot_sync(0xFFFFFFFFu, f == 2);
                if (pmask) {
                    const int px = __ffs(pmask) - 1;   // nearest PREFIX
                    if (lane > px) { vlo = 0; vhi = 0; }
                    done = true;
                }
#pragma unroll
                for (int o = 16; o > 0; o >>= 1) {
                    vlo += __shfl_xor_sync(0xFFFFFFFFu, vlo, o);
                    vhi += __shfl_xor_sync(0xFFFFFFFFu, vhi, o);
                }
                excl_lo += vlo; excl_hi += vhi;
                win++;
            }
            if (lane == 0) {
                g_pre_lo[bid] = excl_lo + loc_lo;      // fieldwise, no carry
                g_pre_hi[bid] = excl_hi + loc_hi;
                __threadfence();
                ((volatile int*)g_flag)[bid] = 2;
            }
        }

        // last chunk publishes per-expert totals for the zero-fill pass
        if (bid == NCHUNK - 1 && lane < N_EXP) {
            const unsigned long long incl =
                (lane < 4) ? (excl_lo + loc_lo) : (excl_hi + loc_hi);
            g_cnt[lane] = (int)((incl >> ((lane & 3) * 16)) & 0xFFFF);
        }

        const int exf = (r < 4)
            ? (int)((excl_lo >> ((r & 3) * 16)) & 0xFFFF)
            : (int)((excl_hi >> ((r & 3) * 16)) & 0xFFFF);
        const int pos = exf + rank;
        sdst[lane] = (pos < CAP) ? (r * CAP + pos) : -1;   // capacity drop
    }
    __syncthreads();

    // ---- phase 4: copy kept rows (each warp: rows warp, warp+8, +16, +24) ----
#pragma unroll
    for (int kk = 0; kk < 4; kk++) {
        const int k = warp + kk * 8;
        const int dst = sdst[k];
        if (dst < 0) continue;
        const float4* s = x + (size_t)(bid * CHUNK + k) * D_VEC;
        float4* o = out + (size_t)dst * D_VEC;
#pragma unroll 4
        for (int j = 0; j < 32; j++)
            o[lane + 32 * j] = __ldg(s + lane + 32 * j);
    }
}

// ---------------------------------------------------------------------------
// Zero-fill: rows [cnt_e, CAP) of each expert. Rows strided by gridDim so an
// expert's zero-tail spreads across many blocks.
// ---------------------------------------------------------------------------
__global__ void __launch_bounds__(256) zerofill_kernel(float4* __restrict__ out)
{
    const float4 z = make_float4(0.f, 0.f, 0.f, 0.f);
    for (int row = blockIdx.x; row < N_TOK; row += gridDim.x) {
        const int e = row >> 11;
        const int p = row & (CAP - 1);
        if (p < g_cnt[e]) continue;          // uniform per block
        float4* o = out + (size_t)row * D_VEC;
#pragma unroll
        for (int i = 0; i < 4; i++)
            o[threadIdx.x + 256 * i] = z;
    }
}

// ---------------------------------------------------------------------------
extern "C" void kernel_launch(void* const* d_in, const int* in_sizes, int n_in,
                              void* d_out, int out_size)
{
    const float* x = (const float*)d_in[0];   // [8,2048,4096]
    const float* W = (const float*)d_in[1];   // [8,4096]
    const float* b = (const float*)d_in[2];   // [8]
    float* out = (float*)d_out;               // [16384,4096]

    reset_kernel<<<1, NCHUNK>>>();
    moe_fused_kernel<<<NCHUNK, 256>>>(
        (const float4*)x, (const float4*)W, b, (float4*)out);
    zerofill_kernel<<<512, 256>>>((float4*)out);
}

// round 15
// speedup vs baseline: 1.1020x; 1.1020x over previous
#include <cuda_runtime.h>
#include <cuda_bf16.h>
#include <cstdint>

// Problem constants (fixed by the reference)
#define N_TOK 16384      // B*S = 8*2048
#define D_DIM 4096
#define D_VEC 1024       // D/4 float4 per row
#define N_EXP 8
#define CAP   2048       // capacity = B*S/E
#define MARGIN_TH 1e-4f  // fp64 re-rank threshold (noise ~1e-6 both sides)

#define NSTAGE 4         // cp.async ring depth
#define STAGE_F4 1024    // 32 tokens x 32 float4 per stage (16KB)

// Scratch (no device allocs allowed) ---------------------------------------
__device__ int   g_routes[N_TOK];
__device__ int   g_inv[N_TOK];    // inv[e*CAP+p] = source token (valid iff p < g_cnt[e])
__device__ int   g_cnt[N_EXP];    // per-expert routed totals
__device__ float g_margin[N_TOK]; // top-2 logit margin per token

// ---------------------------------------------------------------------------
// Pass 1: routing with a cp.async(LDGSTS) smem pipeline. R12's route measured
// DRAM 38% / issue 32% / FMA 20%: latency-bound because x-load latency was
// carried in registers. Here x streams global->smem with no register
// dependency (4-stage ring), .cg bypasses L1 so W (128KB) stays L1-resident.
// 256 thr = 8 warps x 4 tokens = 32 tokens/CTA -> 512 CTAs.
// Lane->dim mapping identical to R12 -> logits bit-identical.
// ---------------------------------------------------------------------------
__global__ void __launch_bounds__(256, 3) route_kernel(
    const float4* __restrict__ x,   // [N_TOK][1024]
    const float4* __restrict__ W,   // [8][1024]
    const float*  __restrict__ b,   // [8]
    int*   __restrict__ routes,
    float* __restrict__ margin)
{
    extern __shared__ float4 sx[];          // [NSTAGE][32 tok][32 f4] = 64KB
    const uint32_t smem_base = (uint32_t)__cvta_generic_to_shared(sx);

    const int tid  = threadIdx.x;
    const int warp = tid >> 5;
    const int lane = tid & 31;
    const int tok0 = blockIdx.x * 32;

    // producer mapping: 8 threads per token, 4 x 16B cp.async each = 512B/stage
    const int ptok = tid >> 3;              // 0..31
    const int poff = (tid & 7) * 4;         // float4 index within stage row
    const float4* gsrc = x + (size_t)(tok0 + ptok) * D_VEC + poff;

    // prefetch stages 0..2
#pragma unroll
    for (int s = 0; s < NSTAGE - 1; s++) {
        const float4* g = gsrc + s * 32;
        uint32_t dst = smem_base + (uint32_t)((s * STAGE_F4 + ptok * 32 + poff) * 16);
#pragma unroll
        for (int o = 0; o < 4; o++)
            asm volatile("cp.async.cg.shared.global [%0], [%1], 16;"
                         :: "r"(dst + o * 16), "l"(g + o));
        asm volatile("cp.async.commit_group;");
    }

    float acc[4][N_EXP];
#pragma unroll
    for (int t = 0; t < 4; t++)
#pragma unroll
        for (int e = 0; e < N_EXP; e++) acc[t][e] = 0.f;

    for (int s = 0; s < 32; s++) {
        asm volatile("cp.async.wait_group 2;");
        __syncthreads();

        const float4* xs = sx + (s & (NSTAGE - 1)) * STAGE_F4 + warp * 4 * 32;
        float4 xv0 = xs[lane];
        float4 xv1 = xs[32 + lane];
        float4 xv2 = xs[64 + lane];
        float4 xv3 = xs[96 + lane];

        const float4* wvp = W + s * 32 + lane;
#pragma unroll
        for (int e = 0; e < N_EXP; e++) {
            float4 wv = __ldg(wvp + e * D_VEC);       // L1-resident
            acc[0][e] += xv0.x * wv.x + xv0.y * wv.y + xv0.z * wv.z + xv0.w * wv.w;
            acc[1][e] += xv1.x * wv.x + xv1.y * wv.y + xv1.z * wv.z + xv1.w * wv.w;
            acc[2][e] += xv2.x * wv.x + xv2.y * wv.y + xv2.z * wv.z + xv2.w * wv.w;
            acc[3][e] += xv3.x * wv.x + xv3.y * wv.y + xv3.z * wv.z + xv3.w * wv.w;
        }
        __syncthreads();                              // all reads of slot done

        if (s + NSTAGE - 1 < 32) {                    // refill freed slot
            const int sn = s + NSTAGE - 1;
            const float4* g = gsrc + sn * 32;
            uint32_t dst = smem_base +
                (uint32_t)((((sn) & (NSTAGE - 1)) * STAGE_F4 + ptok * 32 + poff) * 16);
#pragma unroll
            for (int o = 0; o < 4; o++)
                asm volatile("cp.async.cg.shared.global [%0], [%1], 16;"
                             :: "r"(dst + o * 16), "l"(g + o));
        }
        asm volatile("cp.async.commit_group;");       // empty group at tail: OK
    }

    // butterfly reduce across the warp
#pragma unroll
    for (int t = 0; t < 4; t++)
#pragma unroll
        for (int e = 0; e < N_EXP; e++) {
            float v = acc[t][e];
#pragma unroll
            for (int off = 16; off > 0; off >>= 1)
                v += __shfl_xor_sync(0xFFFFFFFFu, v, off);
            acc[t][e] = v;
        }

    if (lane == 0) {
        const int tbase = tok0 + warp * 4;
#pragma unroll
        for (int t = 0; t < 4; t++) {
            float best = -1e30f, second = -1e30f; int bi = 0;
#pragma unroll
            for (int e = 0; e < N_EXP; e++) {
                float l = acc[t][e] + b[e];
                if (l > best) { second = best; best = l; bi = e; }
                else if (l > second) { second = l; }
            }
            routes[tbase + t] = bi;
            margin[tbase + t] = best - second;
        }
    }
}

// ---------------------------------------------------------------------------
// Pass 1b: fp64 refinement, distributed over 64 blocks (proven form).
// Expected ~4 marginal tokens chip-wide at 1e-4 (noise ~1e-6 -> 100x safety).
// ---------------------------------------------------------------------------
__global__ void __launch_bounds__(256) refine_kernel(
    const float* __restrict__ x,
    const float* __restrict__ W,
    const float* __restrict__ b,
    int* __restrict__ routes)
{
    __shared__ int    list[256];
    __shared__ int    nlist;
    __shared__ double sred[8][N_EXP];

    const int tid  = threadIdx.x;
    const int warp = tid >> 5;
    const int lane = tid & 31;
    const int tok0 = blockIdx.x * 256;

    if (tid == 0) nlist = 0;
    __syncthreads();

    if (g_margin[tok0 + tid] < MARGIN_TH) {
        int s = atomicAdd(&nlist, 1);
        list[s] = tok0 + tid;
    }
    __syncthreads();

    const int n = nlist;
    for (int w = 0; w < n; w++) {
        const int tok = list[w];
        const float* xr = x + (size_t)tok * D_DIM;

        double p[N_EXP];
#pragma unroll
        for (int e = 0; e < N_EXP; e++) p[e] = 0.0;

        for (int d = tid; d < D_DIM; d += 256) {
            const double xv = (double)__ldg(xr + d);
#pragma unroll
            for (int e = 0; e < N_EXP; e++)
                p[e] += xv * (double)__ldg(W + e * D_DIM + d);
        }

#pragma unroll
        for (int e = 0; e < N_EXP; e++) {
            double v = p[e];
#pragma unroll
            for (int off = 16; off > 0; off >>= 1)
                v += __shfl_xor_sync(0xFFFFFFFFu, v, off);
            if (lane == 0) sred[warp][e] = v;
        }
        __syncthreads();

        if (tid == 0) {
            double best = -1e300; int bi = 0;
#pragma unroll
            for (int e = 0; e < N_EXP; e++) {
                double s = (double)b[e];
#pragma unroll
                for (int wi = 0; wi < 8; wi++) s += sred[wi][e];
                if (s > best) { best = s; bi = e; }   // strict > : first-max
            }
            routes[tok] = bi;
        }
        __syncthreads();
    }
}

// ---------------------------------------------------------------------------
// Pass 2: stable positions, register/shfl-based (proven form).
// ---------------------------------------------------------------------------
__global__ void __launch_bounds__(1024) scan_kernel(
    const int4* __restrict__ routes4, int* __restrict__ inv)
{
    __shared__ unsigned long long wtot_lo[32], wtot_hi[32];
    __shared__ unsigned long long base_lo[32], base_hi[32];

    const int t    = threadIdx.x;
    const int warp = t >> 5;
    const int lane = t & 31;

    int toks[16];
    const int4* rp = routes4 + t * 4;
#pragma unroll
    for (int q = 0; q < 4; q++) {
        int4 v = __ldg(rp + q);
        toks[q * 4 + 0] = v.x; toks[q * 4 + 1] = v.y;
        toks[q * 4 + 2] = v.z; toks[q * 4 + 3] = v.w;
    }

    unsigned long long h = 0ull;                       // 8x8-bit histogram
#pragma unroll
    for (int k = 0; k < 16; k++) h += 1ull << (toks[k] * 8);

    unsigned long long g = h >> 32;                    // spread to 4x16-bit
    unsigned long long lo =  (h & 0xFFull)            | ((h & 0xFF00ull) << 8)
                          | ((h & 0xFF0000ull) << 16) | ((h & 0xFF000000ull) << 24);
    unsigned long long hi =  (g & 0xFFull)            | ((g & 0xFF00ull) << 8)
                          | ((g & 0xFF0000ull) << 16) | ((g & 0xFF000000ull) << 24);

    unsigned long long slo = lo, shi = hi;
#pragma unroll
    for (int o = 1; o < 32; o <<= 1) {
        unsigned long long nl = __shfl_up_sync(0xFFFFFFFFu, slo, o);
        unsigned long long nh = __shfl_up_sync(0xFFFFFFFFu, shi, o);
        if (lane >= o) { slo += nl; shi += nh; }
    }
    const unsigned long long elo = slo - lo;
    const unsigned long long ehi = shi - hi;
    if (lane == 31) { wtot_lo[warp] = slo; wtot_hi[warp] = shi; }
    __syncthreads();

    if (warp == 0) {
        unsigned long long tlo = wtot_lo[lane], thi = wtot_hi[lane];
        unsigned long long plo = tlo, phi = thi;
#pragma unroll
        for (int o = 1; o < 32; o <<= 1) {
            unsigned long long nl = __shfl_up_sync(0xFFFFFFFFu, plo, o);
            unsigned long long nh = __shfl_up_sync(0xFFFFFFFFu, phi, o);
            if (lane >= o) { plo += nl; phi += nh; }
        }
        base_lo[lane] = plo - tlo;
        base_hi[lane] = phi - thi;
        if (lane == 31) {
#pragma unroll
            for (int e = 0; e < 4; e++) {
                g_cnt[e]     = (int)((plo >> (e * 16)) & 0xFFFF);
                g_cnt[e + 4] = (int)((phi >> (e * 16)) & 0xFFFF);
            }
        }
    }
    __syncthreads();

    unsigned long long mylo = elo + base_lo[warp];
    unsigned long long myhi = ehi + base_hi[warp];
    const int base = t * 16;
#pragma unroll
    for (int k = 0; k < 16; k++) {
        const int r = toks[k];
        const int sh = (r & 3) * 16;
        const bool low = r < 4;
        const int p = (int)(((low ? mylo : myhi) >> sh) & 0xFFFF);
        const unsigned long long inc = 1ull << sh;
        if (low) mylo += inc; else myhi += inc;
        if (p < CAP) inv[r * CAP + p] = base + k;
    }
}

// ---------------------------------------------------------------------------
// Pass 3: gather (proven R10 form, 77us @78% DRAM). One CTA per output row;
// writes zeros for empty capacity slots.
// ---------------------------------------------------------------------------
__global__ void __launch_bounds__(256) gather_kernel(
    const float4* __restrict__ x,
    const int*   __restrict__ inv,
    float4* __restrict__ out)
{
    const int row = blockIdx.x;
    const int e = row >> 11;          // row / CAP
    const int p = row & (CAP - 1);
    float4* o = out + (size_t)row * D_VEC;
    const int t = threadIdx.x;

    if (p < g_cnt[e]) {
        const int src = __ldg(inv + row);      // uniform broadcast
        const float4* s = x + (size_t)src * D_VEC;
#pragma unroll
        for (int i = 0; i < 4; i++)
            o[t + 256 * i] = __ldg(s + t + 256 * i);
    } else {
        const float4 z = make_float4(0.f, 0.f, 0.f, 0.f);
#pragma unroll
        for (int i = 0; i < 4; i++)
            o[t + 256 * i] = z;
    }
}

// ---------------------------------------------------------------------------
extern "C" void kernel_launch(void* const* d_in, const int* in_sizes, int n_in,
                              void* d_out, int out_size)
{
    const float* x = (const float*)d_in[0];   // [8,2048,4096]
    const float* W = (const float*)d_in[1];   // [8,4096]
    const float* b = (const float*)d_in[2];   // [8]
    float* out = (float*)d_out;               // [16384,4096]

    int* routes;   cudaGetSymbolAddress((void**)&routes, g_routes);
    int* inv;      cudaGetSymbolAddress((void**)&inv,    g_inv);
    float* margin; cudaGetSymbolAddress((void**)&margin, g_margin);

    static bool attr_done = false;
    if (!attr_done) {
        cudaFuncSetAttribute(route_kernel,
                             cudaFuncAttributeMaxDynamicSharedMemorySize,
                             NSTAGE * STAGE_F4 * 16);   // 64KB
        attr_done = true;
    }

    route_kernel<<<N_TOK / 32, 256, NSTAGE * STAGE_F4 * 16>>>(
        (const float4*)x, (const float4*)W, b, routes, margin);
    refine_kernel<<<64, 256>>>(x, W, b, routes);
    scan_kernel<<<1, 1024>>>((const int4*)routes, inv);
    gather_kernel<<<N_TOK, 256>>>(
        (const float4*)x, inv, (float4*)out);
}

// round 16
// speedup vs baseline: 1.1674x; 1.0594x over previous
#include <cuda_runtime.h>
#include <cuda_bf16.h>
#include <cstdint>

// Problem constants (fixed by the reference)
#define N_TOK 16384      // B*S = 8*2048
#define D_DIM 4096
#define D_VEC 1024       // D/4 float4 per row
#define N_EXP 8
#define CAP   2048       // capacity = B*S/E
#define MARGIN_TH 1e-4f  // fp64 re-rank threshold (noise ~1e-6 both sides)

// Scratch (no device allocs allowed) ---------------------------------------
__device__ int   g_routes[N_TOK];
__device__ int   g_inv[N_TOK];    // inv[e*CAP+p] = source token (valid iff p < g_cnt[e])
__device__ int   g_cnt[N_EXP];    // per-expert routed totals
__device__ float g_margin[N_TOK]; // top-2 logit margin per token

// ---------------------------------------------------------------------------
// Pass 1: routing — R12's kernel verbatim (measured 90.5us; best of all five
// route variants tried: 2tok/warp ~118, smem-W ~110, f32x2 ~115, cp.async
// with 64KB smem ~118 [smem carveout left 36KB L1 -> W evicted to L2]).
// 4 tokens/warp, scalar fp32, plain __ldg; W rides L1, x streams DRAM.
// 32 tokens/CTA -> 512 CTAs, 3 CTAs/SM.
// ---------------------------------------------------------------------------
__global__ void __launch_bounds__(256, 3) route_kernel(
    const float4* __restrict__ x,   // [N_TOK][1024]
    const float4* __restrict__ W,   // [8][1024]
    const float*  __restrict__ b,   // [8]
    int*   __restrict__ routes,
    float* __restrict__ margin)
{
    const int warp = threadIdx.x >> 5;
    const int lane = threadIdx.x & 31;
    const int tbase = (blockIdx.x * 8 + warp) * 4;   // first of 4 tokens

    const float4* x0 = x + (size_t)tbase * D_VEC;

    float acc[4][N_EXP];
#pragma unroll
    for (int t = 0; t < 4; t++)
#pragma unroll
        for (int e = 0; e < N_EXP; e++) acc[t][e] = 0.f;

    for (int i = 0; i < 32; i++) {
        const int idx = i * 32 + lane;
        float4 xv0 = __ldg(x0 + idx);
        float4 xv1 = __ldg(x0 + D_VEC + idx);
        float4 xv2 = __ldg(x0 + 2 * D_VEC + idx);
        float4 xv3 = __ldg(x0 + 3 * D_VEC + idx);
#pragma unroll
        for (int e = 0; e < N_EXP; e++) {
            float4 wv = __ldg(W + e * D_VEC + idx);   // L1-resident
            acc[0][e] += xv0.x * wv.x + xv0.y * wv.y + xv0.z * wv.z + xv0.w * wv.w;
            acc[1][e] += xv1.x * wv.x + xv1.y * wv.y + xv1.z * wv.z + xv1.w * wv.w;
            acc[2][e] += xv2.x * wv.x + xv2.y * wv.y + xv2.z * wv.z + xv2.w * wv.w;
            acc[3][e] += xv3.x * wv.x + xv3.y * wv.y + xv3.z * wv.z + xv3.w * wv.w;
        }
    }

    // butterfly reduce across the warp
#pragma unroll
    for (int t = 0; t < 4; t++) {
#pragma unroll
        for (int e = 0; e < N_EXP; e++) {
            float v = acc[t][e];
#pragma unroll
            for (int off = 16; off > 0; off >>= 1)
                v += __shfl_xor_sync(0xFFFFFFFFu, v, off);
            acc[t][e] = v;
        }
    }

    if (lane == 0) {
#pragma unroll
        for (int t = 0; t < 4; t++) {
            float best = -1e30f, second = -1e30f;
            int bi = 0;
#pragma unroll
            for (int e = 0; e < N_EXP; e++) {
                float l = acc[t][e] + b[e];
                if (l > best) { second = best; best = l; bi = e; }
                else if (l > second) { second = l; }
            }
            routes[tbase + t] = bi;
            margin[tbase + t] = best - second;
        }
    }
}

// ---------------------------------------------------------------------------
// Pass 1b: fp64 refinement, distributed over 64 blocks (proven form).
// Expected ~4 marginal tokens chip-wide at 1e-4 (noise ~1e-6 -> 100x safety).
// ---------------------------------------------------------------------------
__global__ void __launch_bounds__(256) refine_kernel(
    const float* __restrict__ x,
    const float* __restrict__ W,
    const float* __restrict__ b,
    int* __restrict__ routes)
{
    __shared__ int    list[256];
    __shared__ int    nlist;
    __shared__ double sred[8][N_EXP];

    const int tid  = threadIdx.x;
    const int warp = tid >> 5;
    const int lane = tid & 31;
    const int tok0 = blockIdx.x * 256;

    if (tid == 0) nlist = 0;
    __syncthreads();

    if (g_margin[tok0 + tid] < MARGIN_TH) {
        int s = atomicAdd(&nlist, 1);
        list[s] = tok0 + tid;
    }
    __syncthreads();

    const int n = nlist;
    for (int w = 0; w < n; w++) {
        const int tok = list[w];
        const float* xr = x + (size_t)tok * D_DIM;

        double p[N_EXP];
#pragma unroll
        for (int e = 0; e < N_EXP; e++) p[e] = 0.0;

        for (int d = tid; d < D_DIM; d += 256) {
            const double xv = (double)__ldg(xr + d);
#pragma unroll
            for (int e = 0; e < N_EXP; e++)
                p[e] += xv * (double)__ldg(W + e * D_DIM + d);
        }

#pragma unroll
        for (int e = 0; e < N_EXP; e++) {
            double v = p[e];
#pragma unroll
            for (int off = 16; off > 0; off >>= 1)
                v += __shfl_xor_sync(0xFFFFFFFFu, v, off);
            if (lane == 0) sred[warp][e] = v;
        }
        __syncthreads();

        if (tid == 0) {
            double best = -1e300; int bi = 0;
#pragma unroll
            for (int e = 0; e < N_EXP; e++) {
                double s = (double)b[e];
#pragma unroll
                for (int wi = 0; wi < 8; wi++) s += sred[wi][e];
                if (s > best) { best = s; bi = e; }   // strict > : first-max
            }
            routes[tok] = bi;
        }
        __syncthreads();
    }
}

// ---------------------------------------------------------------------------
// Pass 2: stable positions, register/shfl-based (proven form). 1024 threads
// x 16 tokens; packed u64 histogram + 3-level shfl scan; no inv init.
// ---------------------------------------------------------------------------
__global__ void __launch_bounds__(1024) scan_kernel(
    const int4* __restrict__ routes4, int* __restrict__ inv)
{
    __shared__ unsigned long long wtot_lo[32], wtot_hi[32];
    __shared__ unsigned long long base_lo[32], base_hi[32];

    const int t    = threadIdx.x;
    const int warp = t >> 5;
    const int lane = t & 31;

    int toks[16];
    const int4* rp = routes4 + t * 4;
#pragma unroll
    for (int q = 0; q < 4; q++) {
        int4 v = __ldg(rp + q);
        toks[q * 4 + 0] = v.x; toks[q * 4 + 1] = v.y;
        toks[q * 4 + 2] = v.z; toks[q * 4 + 3] = v.w;
    }

    unsigned long long h = 0ull;                       // 8x8-bit histogram
#pragma unroll
    for (int k = 0; k < 16; k++) h += 1ull << (toks[k] * 8);

    unsigned long long g = h >> 32;                    // spread to 4x16-bit
    unsigned long long lo =  (h & 0xFFull)            | ((h & 0xFF00ull) << 8)
                          | ((h & 0xFF0000ull) << 16) | ((h & 0xFF000000ull) << 24);
    unsigned long long hi =  (g & 0xFFull)            | ((g & 0xFF00ull) << 8)
                          | ((g & 0xFF0000ull) << 16) | ((g & 0xFF000000ull) << 24);

    unsigned long long slo = lo, shi = hi;
#pragma unroll
    for (int o = 1; o < 32; o <<= 1) {
        unsigned long long nl = __shfl_up_sync(0xFFFFFFFFu, slo, o);
        unsigned long long nh = __shfl_up_sync(0xFFFFFFFFu, shi, o);
        if (lane >= o) { slo += nl; shi += nh; }
    }
    const unsigned long long elo = slo - lo;
    const unsigned long long ehi = shi - hi;
    if (lane == 31) { wtot_lo[warp] = slo; wtot_hi[warp] = shi; }
    __syncthreads();

    if (warp == 0) {
        unsigned long long tlo = wtot_lo[lane], thi = wtot_hi[lane];
        unsigned long long plo = tlo, phi = thi;
#pragma unroll
        for (int o = 1; o < 32; o <<= 1) {
            unsigned long long nl = __shfl_up_sync(0xFFFFFFFFu, plo, o);
            unsigned long long nh = __shfl_up_sync(0xFFFFFFFFu, phi, o);
            if (lane >= o) { plo += nl; phi += nh; }
        }
        base_lo[lane] = plo - tlo;
        base_hi[lane] = phi - thi;
        if (lane == 31) {
#pragma unroll
            for (int e = 0; e < 4; e++) {
                g_cnt[e]     = (int)((plo >> (e * 16)) & 0xFFFF);
                g_cnt[e + 4] = (int)((phi >> (e * 16)) & 0xFFFF);
            }
        }
    }
    __syncthreads();

    unsigned long long mylo = elo + base_lo[warp];
    unsigned long long myhi = ehi + base_hi[warp];
    const int base = t * 16;
#pragma unroll
    for (int k = 0; k < 16; k++) {
        const int r = toks[k];
        const int sh = (r & 3) * 16;
        const bool low = r < 4;
        const int p = (int)(((low ? mylo : myhi) >> sh) & 0xFFFF);
        const unsigned long long inc = 1ull << sh;
        if (low) mylo += inc; else myhi += inc;
        if (p < CAP) inv[r * CAP + p] = base + k;
    }
}

// ---------------------------------------------------------------------------
// Pass 3: gather (proven form, 77us @78% DRAM across three rounds). One CTA
// per output row; zeros for empty capacity slots.
// ---------------------------------------------------------------------------
__global__ void __launch_bounds__(256) gather_kernel(
    const float4* __restrict__ x,
    const int*   __restrict__ inv,
    float4* __restrict__ out)
{
    const int row = blockIdx.x;
    const int e = row >> 11;          // row / CAP
    const int p = row & (CAP - 1);
    float4* o = out + (size_t)row * D_VEC;
    const int t = threadIdx.x;

    if (p < g_cnt[e]) {
        const int src = __ldg(inv + row);      // uniform broadcast
        const float4* s = x + (size_t)src * D_VEC;
#pragma unroll
        for (int i = 0; i < 4; i++)
            o[t + 256 * i] = __ldg(s + t + 256 * i);
    } else {
        const float4 z = make_float4(0.f, 0.f, 0.f, 0.f);
#pragma unroll
        for (int i = 0; i < 4; i++)
            o[t + 256 * i] = z;
    }
}

// ---------------------------------------------------------------------------
extern "C" void kernel_launch(void* const* d_in, const int* in_sizes, int n_in,
                              void* d_out, int out_size)
{
    const float* x = (const float*)d_in[0];   // [8,2048,4096]
    const float* W = (const float*)d_in[1];   // [8,4096]
    const float* b = (const float*)d_in[2];   // [8]
    float* out = (float*)d_out;               // [16384,4096]

    int* routes;   cudaGetSymbolAddress((void**)&routes, g_routes);
    int* inv;      cudaGetSymbolAddress((void**)&inv,    g_inv);
    float* margin; cudaGetSymbolAddress((void**)&margin, g_margin);

    route_kernel<<<N_TOK / 32, 256>>>(
        (const float4*)x, (const float4*)W, b, routes, margin);
    refine_kernel<<<64, 256>>>(x, W, b, routes);
    scan_kernel<<<1, 1024>>>((const int4*)routes, inv);
    gather_kernel<<<N_TOK, 256>>>(
        (const float4*)x, inv, (float4*)out);
}

// round 17
// speedup vs baseline: 1.1965x; 1.0249x over previous
#include <cuda_runtime.h>
#include <cuda_bf16.h>
#include <cstdint>

// Problem constants (fixed by the reference)
#define N_TOK 16384      // B*S = 8*2048
#define D_DIM 4096
#define D_VEC 1024       // D/4 float4 per row
#define N_EXP 8
#define CAP   2048       // capacity = B*S/E
#define MARGIN_TH 1e-4f  // fp64 re-rank threshold (noise ~1e-6 both sides)

// Scratch (no device allocs allowed) ---------------------------------------
__device__ int   g_routes[N_TOK];
__device__ int   g_inv[N_TOK];    // inv[e*CAP+p] = source token (valid iff p < g_cnt[e])
__device__ int   g_cnt[N_EXP];    // per-expert routed totals
__device__ float g_margin[N_TOK]; // top-2 logit margin per token

// ---------------------------------------------------------------------------
// Pass 1: routing — R12 structure (90.5us measured) with ONE change:
// x loads use __ldcg (ld.global.cg, L2-only, no L1 allocation). Theory: the
// x stream was evicting W's 128KB from L1, forcing W loads to ~240cyc L2
// hits that 24 warps/SM cannot hide (ncu: nothing saturated, issue=32%).
// With x bypassing L1, W (128KB < 228KB L1) becomes truly L1-resident
// (~39cyc) and the FMA chain unblocks.
// 4 tokens/warp, 32 tokens/CTA -> 512 CTAs, 3 CTAs/SM.
// ---------------------------------------------------------------------------
__global__ void __launch_bounds__(256, 3) route_kernel(
    const float4* __restrict__ x,   // [N_TOK][1024]
    const float4* __restrict__ W,   // [8][1024]
    const float*  __restrict__ b,   // [8]
    int*   __restrict__ routes,
    float* __restrict__ margin)
{
    const int warp = threadIdx.x >> 5;
    const int lane = threadIdx.x & 31;
    const int tbase = (blockIdx.x * 8 + warp) * 4;   // first of 4 tokens

    const float4* x0 = x + (size_t)tbase * D_VEC;

    float acc[4][N_EXP];
#pragma unroll
    for (int t = 0; t < 4; t++)
#pragma unroll
        for (int e = 0; e < N_EXP; e++) acc[t][e] = 0.f;

    for (int i = 0; i < 32; i++) {
        const int idx = i * 32 + lane;
        float4 xv0 = __ldcg(x0 + idx);                // L2-only: protect W's L1
        float4 xv1 = __ldcg(x0 + D_VEC + idx);
        float4 xv2 = __ldcg(x0 + 2 * D_VEC + idx);
        float4 xv3 = __ldcg(x0 + 3 * D_VEC + idx);
#pragma unroll
        for (int e = 0; e < N_EXP; e++) {
            float4 wv = __ldg(W + e * D_VEC + idx);   // L1-resident
            acc[0][e] += xv0.x * wv.x + xv0.y * wv.y + xv0.z * wv.z + xv0.w * wv.w;
            acc[1][e] += xv1.x * wv.x + xv1.y * wv.y + xv1.z * wv.z + xv1.w * wv.w;
            acc[2][e] += xv2.x * wv.x + xv2.y * wv.y + xv2.z * wv.z + xv2.w * wv.w;
            acc[3][e] += xv3.x * wv.x + xv3.y * wv.y + xv3.z * wv.z + xv3.w * wv.w;
        }
    }

    // butterfly reduce across the warp
#pragma unroll
    for (int t = 0; t < 4; t++) {
#pragma unroll
        for (int e = 0; e < N_EXP; e++) {
            float v = acc[t][e];
#pragma unroll
            for (int off = 16; off > 0; off >>= 1)
                v += __shfl_xor_sync(0xFFFFFFFFu, v, off);
            acc[t][e] = v;
        }
    }

    if (lane == 0) {
#pragma unroll
        for (int t = 0; t < 4; t++) {
            float best = -1e30f, second = -1e30f;
            int bi = 0;
#pragma unroll
            for (int e = 0; e < N_EXP; e++) {
                float l = acc[t][e] + b[e];
                if (l > best) { second = best; best = l; bi = e; }
                else if (l > second) { second = l; }
            }
            routes[tbase + t] = bi;
            margin[tbase + t] = best - second;
        }
    }
}

// ---------------------------------------------------------------------------
// Pass 1b: fp64 refinement, distributed over 64 blocks (proven form).
// Expected ~4 marginal tokens chip-wide at 1e-4 (noise ~1e-6 -> 100x safety).
// ---------------------------------------------------------------------------
__global__ void __launch_bounds__(256) refine_kernel(
    const float* __restrict__ x,
    const float* __restrict__ W,
    const float* __restrict__ b,
    int* __restrict__ routes)
{
    __shared__ int    list[256];
    __shared__ int    nlist;
    __shared__ double sred[8][N_EXP];

    const int tid  = threadIdx.x;
    const int warp = tid >> 5;
    const int lane = tid & 31;
    const int tok0 = blockIdx.x * 256;

    if (tid == 0) nlist = 0;
    __syncthreads();

    if (g_margin[tok0 + tid] < MARGIN_TH) {
        int s = atomicAdd(&nlist, 1);
        list[s] = tok0 + tid;
    }
    __syncthreads();

    const int n = nlist;
    for (int w = 0; w < n; w++) {
        const int tok = list[w];
        const float* xr = x + (size_t)tok * D_DIM;

        double p[N_EXP];
#pragma unroll
        for (int e = 0; e < N_EXP; e++) p[e] = 0.0;

        for (int d = tid; d < D_DIM; d += 256) {
            const double xv = (double)__ldg(xr + d);
#pragma unroll
            for (int e = 0; e < N_EXP; e++)
                p[e] += xv * (double)__ldg(W + e * D_DIM + d);
        }

#pragma unroll
        for (int e = 0; e < N_EXP; e++) {
            double v = p[e];
#pragma unroll
            for (int off = 16; off > 0; off >>= 1)
                v += __shfl_xor_sync(0xFFFFFFFFu, v, off);
            if (lane == 0) sred[warp][e] = v;
        }
        __syncthreads();

        if (tid == 0) {
            double best = -1e300; int bi = 0;
#pragma unroll
            for (int e = 0; e < N_EXP; e++) {
                double s = (double)b[e];
#pragma unroll
                for (int wi = 0; wi < 8; wi++) s += sred[wi][e];
                if (s > best) { best = s; bi = e; }   // strict > : first-max
            }
            routes[tok] = bi;
        }
        __syncthreads();
    }
}

// ---------------------------------------------------------------------------
// Pass 2: stable positions, register/shfl-based (proven form). 1024 threads
// x 16 tokens; packed u64 histogram + 3-level shfl scan; no inv init.
// ---------------------------------------------------------------------------
__global__ void __launch_bounds__(1024) scan_kernel(
    const int4* __restrict__ routes4, int* __restrict__ inv)
{
    __shared__ unsigned long long wtot_lo[32], wtot_hi[32];
    __shared__ unsigned long long base_lo[32], base_hi[32];

    const int t    = threadIdx.x;
    const int warp = t >> 5;
    const int lane = t & 31;

    int toks[16];
    const int4* rp = routes4 + t * 4;
#pragma unroll
    for (int q = 0; q < 4; q++) {
        int4 v = __ldg(rp + q);
        toks[q * 4 + 0] = v.x; toks[q * 4 + 1] = v.y;
        toks[q * 4 + 2] = v.z; toks[q * 4 + 3] = v.w;
    }

    unsigned long long h = 0ull;                       // 8x8-bit histogram
#pragma unroll
    for (int k = 0; k < 16; k++) h += 1ull << (toks[k] * 8);

    unsigned long long g = h >> 32;                    // spread to 4x16-bit
    unsigned long long lo =  (h & 0xFFull)            | ((h & 0xFF00ull) << 8)
                          | ((h & 0xFF0000ull) << 16) | ((h & 0xFF000000ull) << 24);
    unsigned long long hi =  (g & 0xFFull)            | ((g & 0xFF00ull) << 8)
                          | ((g & 0xFF0000ull) << 16) | ((g & 0xFF000000ull) << 24);

    unsigned long long slo = lo, shi = hi;
#pragma unroll
    for (int o = 1; o < 32; o <<= 1) {
        unsigned long long nl = __shfl_up_sync(0xFFFFFFFFu, slo, o);
        unsigned long long nh = __shfl_up_sync(0xFFFFFFFFu, shi, o);
        if (lane >= o) { slo += nl; shi += nh; }
    }
    const unsigned long long elo = slo - lo;
    const unsigned long long ehi = shi - hi;
    if (lane == 31) { wtot_lo[warp] = slo; wtot_hi[warp] = shi; }
    __syncthreads();

    if (warp == 0) {
        unsigned long long tlo = wtot_lo[lane], thi = wtot_hi[lane];
        unsigned long long plo = tlo, phi = thi;
#pragma unroll
        for (int o = 1; o < 32; o <<= 1) {
            unsigned long long nl = __shfl_up_sync(0xFFFFFFFFu, plo, o);
            unsigned long long nh = __shfl_up_sync(0xFFFFFFFFu, phi, o);
            if (lane >= o) { plo += nl; phi += nh; }
        }
        base_lo[lane] = plo - tlo;
        base_hi[lane] = phi - thi;
        if (lane == 31) {
#pragma unroll
            for (int e = 0; e < 4; e++) {
                g_cnt[e]     = (int)((plo >> (e * 16)) & 0xFFFF);
                g_cnt[e + 4] = (int)((phi >> (e * 16)) & 0xFFFF);
            }
        }
    }
    __syncthreads();

    unsigned long long mylo = elo + base_lo[warp];
    unsigned long long myhi = ehi + base_hi[warp];
    const int base = t * 16;
#pragma unroll
    for (int k = 0; k < 16; k++) {
        const int r = toks[k];
        const int sh = (r & 3) * 16;
        const bool low = r < 4;
        const int p = (int)(((low ? mylo : myhi) >> sh) & 0xFFFF);
        const unsigned long long inc = 1ull << sh;
        if (low) mylo += inc; else myhi += inc;
        if (p < CAP) inv[r * CAP + p] = base + k;
    }
}

// ---------------------------------------------------------------------------
// Pass 3: gather (proven form, 77us @78% DRAM across four rounds). One CTA
// per output row; zeros for empty capacity slots.
// ---------------------------------------------------------------------------
__global__ void __launch_bounds__(256) gather_kernel(
    const float4* __restrict__ x,
    const int*   __restrict__ inv,
    float4* __restrict__ out)
{
    const int row = blockIdx.x;
    const int e = row >> 11;          // row / CAP
    const int p = row & (CAP - 1);
    float4* o = out + (size_t)row * D_VEC;
    const int t = threadIdx.x;

    if (p < g_cnt[e]) {
        const int src = __ldg(inv + row);      // uniform broadcast
        const float4* s = x + (size_t)src * D_VEC;
#pragma unroll
        for (int i = 0; i < 4; i++)
            o[t + 256 * i] = __ldg(s + t + 256 * i);
    } else {
        const float4 z = make_float4(0.f, 0.f, 0.f, 0.f);
#pragma unroll
        for (int i = 0; i < 4; i++)
            o[t + 256 * i] = z;
    }
}

// ---------------------------------------------------------------------------
extern "C" void kernel_launch(void* const* d_in, const int* in_sizes, int n_in,
                              void* d_out, int out_size)
{
    const float* x = (const float*)d_in[0];   // [8,2048,4096]
    const float* W = (const float*)d_in[1];   // [8,4096]
    const float* b = (const float*)d_in[2];   // [8]
    float* out = (float*)d_out;               // [16384,4096]

    int* routes;   cudaGetSymbolAddress((void**)&routes, g_routes);
    int* inv;      cudaGetSymbolAddress((void**)&inv,    g_inv);
    float* margin; cudaGetSymbolAddress((void**)&margin, g_margin);

    route_kernel<<<N_TOK / 32, 256>>>(
        (const float4*)x, (const float4*)W, b, routes, margin);
    refine_kernel<<<64, 256>>>(x, W, b, routes);
    scan_kernel<<<1, 1024>>>((const int4*)routes, inv);
    gather_kernel<<<N_TOK, 256>>>(
        (const float4*)x, inv, (float4*)out);
}